// round 15
// baseline (speedup 1.0000x reference)
#include <cuda_runtime.h>

// out[b, p, d] = x[b, p] * W[p, d] + bias[p, d]
// B=64, P=2000, D=512 (fp32). Converged shape at the HBM write roofline
// (~6.7TB/s pure writes): thread = one (p,d4) float4 column x 8 batch rows,
// grid 1000x8x256, W/b L2-resident.
//
// Store-policy axis final point: .wt (write-through) vs .cs (39.4us) vs
// default (45.6us). Hypothesis: .wt removes L2 dirty-line occupancy entirely
// (whole L2 free for W/b/x, write stream visible to the MC earlier) — or it
// loses L2 write batching and regresses. One run decides.

#define B_DIM 64
#define P_DIM 2000
#define D_DIM 512
#define D4 (D_DIM / 4)              // 128
#define PD4 (P_DIM * D4)            // 256000
#define B_CHUNK 8                   // batches per thread
#define N_CHUNKS (B_DIM / B_CHUNK)  // 8

__device__ __forceinline__ void stg128_wt(float4* p, float4 v) {
    asm volatile("st.global.wt.v4.f32 [%0], {%1,%2,%3,%4};"
                 :: "l"(p), "f"(v.x), "f"(v.y), "f"(v.z), "f"(v.w)
                 : "memory");
}

__global__ __launch_bounds__(256) void feature_expander_kernel(
    const float* __restrict__ x,      // [B, P]
    const float4* __restrict__ W,     // [P, D/4]
    const float4* __restrict__ bias,  // [P, D/4]
    float4* __restrict__ out)         // [B, P, D/4]
{
    int idx = blockIdx.x * blockDim.x + threadIdx.x;   // < PD4 always (1000*256)
    int p = idx >> 7;                                  // idx / 128
    int b0 = blockIdx.y * B_CHUNK;

    float4 w = __ldg(&W[idx]);
    float4 bv = __ldg(&bias[idx]);

    const float* xp = x + b0 * P_DIM + p;
    float4* op = out + (size_t)b0 * PD4 + idx;

    #pragma unroll
    for (int i = 0; i < B_CHUNK; i++) {
        float xv = __ldg(xp + i * P_DIM);
        float4 o;
        o.x = fmaf(xv, w.x, bv.x);
        o.y = fmaf(xv, w.y, bv.y);
        o.z = fmaf(xv, w.z, bv.z);
        o.w = fmaf(xv, w.w, bv.w);
        stg128_wt(op + (size_t)i * PD4, o);   // write-through store
    }
}

extern "C" void kernel_launch(void* const* d_in, const int* in_sizes, int n_in,
                              void* d_out, int out_size) {
    const float*  x  = (const float*)d_in[0];
    const float4* W  = (const float4*)d_in[1];
    const float4* bb = (const float4*)d_in[2];
    float4* out = (float4*)d_out;

    dim3 grid(PD4 / 256, N_CHUNKS);   // 1000 x 8
    feature_expander_kernel<<<grid, 256>>>(x, W, bb, out);
}

// round 16
// speedup vs baseline: 1.1615x; 1.1615x over previous
#include <cuda_runtime.h>

// out[b, p, d] = x[b, p] * W[p, d] + bias[p, d]
// B=64, P=2000, D=512 (fp32).
//
// FINAL — converged at the HBM write roofline: 262MB output / ~39us =
// ~6.7TB/s sustained pure writes (reads ~8.5MB, fully L2-resident; all
// compute pipes <6% busy).
//
// Every axis A/B'd on GB300 hardware across 15 rounds:
//   B_CHUNK:      4->60.1us, 8->39.4us, 16->41.0us           (8 wins)
//   TPB:          128->40.4us, 256->39.4us, 512->40.9us       (256 best)
//   scheduling:   HW grid 39.4us, persistent 1184 45.4us      (HW wins)
//   access width: 128-bit 39.4us, 256-bit v8.f32 45.1us       (MLP > instr count)
//   store policy: .cs 39.4us, default 45.6us, .wt 45.8us      (.cs load-bearing:
//                 output must stage in L2 for writeback batching but with
//                 evict-first priority so W/b stay resident)
//   x prefetch:   neutral (ptxas already optimal, regs=32)
//
// Shape: thread = one (p, d4) float4 column x 8 batch rows, grid 1000x8x256.
// W/b loaded once per thread (re-reads hit L2; W+b = 8MB resident). x loads
// are per-warp broadcasts (L1 hits). Streaming .cs stores.

#define B_DIM 64
#define P_DIM 2000
#define D_DIM 512
#define D4 (D_DIM / 4)              // 128
#define PD4 (P_DIM * D4)            // 256000
#define B_CHUNK 8                   // batches per thread
#define N_CHUNKS (B_DIM / B_CHUNK)  // 8

__global__ __launch_bounds__(256) void feature_expander_kernel(
    const float* __restrict__ x,      // [B, P]
    const float4* __restrict__ W,     // [P, D/4]
    const float4* __restrict__ bias,  // [P, D/4]
    float4* __restrict__ out)         // [B, P, D/4]
{
    int idx = blockIdx.x * blockDim.x + threadIdx.x;   // < PD4 always (1000*256)
    int p = idx >> 7;                                  // idx / 128
    int b0 = blockIdx.y * B_CHUNK;

    float4 w = __ldg(&W[idx]);
    float4 bv = __ldg(&bias[idx]);

    const float* xp = x + b0 * P_DIM + p;
    float4* op = out + (size_t)b0 * PD4 + idx;

    #pragma unroll
    for (int i = 0; i < B_CHUNK; i++) {
        float xv = __ldg(xp + i * P_DIM);
        float4 o;
        o.x = fmaf(xv, w.x, bv.x);
        o.y = fmaf(xv, w.y, bv.y);
        o.z = fmaf(xv, w.z, bv.z);
        o.w = fmaf(xv, w.w, bv.w);
        __stcs(op + (size_t)i * PD4, o);   // streaming store (evict-first)
    }
}

extern "C" void kernel_launch(void* const* d_in, const int* in_sizes, int n_in,
                              void* d_out, int out_size) {
    const float*  x  = (const float*)d_in[0];
    const float4* W  = (const float4*)d_in[1];
    const float4* bb = (const float4*)d_in[2];
    float4* out = (float4*)d_out;

    dim3 grid(PD4 / 256, N_CHUNKS);   // 1000 x 8
    feature_expander_kernel<<<grid, 256>>>(x, W, bb, out);
}